// round 1
// baseline (speedup 1.0000x reference)
#include <cuda_runtime.h>

#define CC 2
#define FF 32
#define HH 1024
#define BB 16
#define SS 2048
#define SF (SS + FF)   // 2080

// ---- scratch (device globals; no allocation allowed) ----
__device__ float g_Mc[(size_t)CC * HH * HH];        // Wq^T @ Wk, per channel   (8 MB)
__device__ float g_E[(size_t)CC * FF * HH];         // emb @ Wk                 (256 KB)
__device__ float g_T[(size_t)CC * BB * SS * HH];    // hidden @ Mc              (256 MB)
__device__ float g_wvs[CC * HH];                    // sum_o Wv[c,o,:]
__device__ float g_vsum[(size_t)CC * BB * SS];      // hidden . wvs

// ---------------------------------------------------------------------------
// wvs[c,h] = sum_o Wv[c,o,h]
__global__ void k_wvsum(const float* __restrict__ Wv) {
    int c = blockIdx.y;
    int h = blockIdx.x * 256 + threadIdx.x;
    const float* W = Wv + (size_t)c * HH * HH;
    float a = 0.f;
#pragma unroll 8
    for (int o = 0; o < HH; ++o) a += W[(size_t)o * HH + h];
    g_wvs[c * HH + h] = a;
}

// vsum[c, bs] = hidden[bs,:] . wvs[c,:]   (one warp per bs, both channels)
__global__ void k_vsum(const float* __restrict__ hidden) {
    int w = (blockIdx.x * blockDim.x + threadIdx.x) >> 5;
    int lane = threadIdx.x & 31;
    if (w >= BB * SS) return;
    const float* hr = hidden + (size_t)w * HH;
    float a0 = 0.f, a1 = 0.f;
#pragma unroll 4
    for (int i = lane; i < HH; i += 32) {
        float hv = hr[i];
        a0 += hv * g_wvs[i];
        a1 += hv * g_wvs[HH + i];
    }
#pragma unroll
    for (int off = 16; off; off >>= 1) {
        a0 += __shfl_down_sync(0xFFFFFFFFu, a0, off);
        a1 += __shfl_down_sync(0xFFFFFFFFu, a1, off);
    }
    if (lane == 0) {
        g_vsum[w] = a0;
        g_vsum[(size_t)BB * SS + w] = a1;
    }
}

// ---------------------------------------------------------------------------
// Mc[c] = Wq[c]^T @ Wk[c]   (TN: both operands K(=o)-major)
__global__ __launch_bounds__(256) void k_Mc(const float* __restrict__ Wq,
                                            const float* __restrict__ Wk) {
    int c = blockIdx.z;
    const float* A = Wq + (size_t)c * HH * HH;   // [o, h1]
    const float* Bm = Wk + (size_t)c * HH * HH;  // [o, h2]
    float* Cc = g_Mc + (size_t)c * HH * HH;
    int tileM = blockIdx.y * 128, tileN = blockIdx.x * 128;
    __shared__ float As[8][128], Bs[8][128];
    int tid = threadIdx.x;
    int lk = tid >> 5, lc = (tid & 31) * 4;
    int rowBase = (tid >> 4) * 8, colBase = (tid & 15) * 8;
    float acc[8][8] = {};
    for (int k0 = 0; k0 < HH; k0 += 8) {
        *(float4*)&As[lk][lc] = *(const float4*)&A[(size_t)(k0 + lk) * HH + tileM + lc];
        *(float4*)&Bs[lk][lc] = *(const float4*)&Bm[(size_t)(k0 + lk) * HH + tileN + lc];
        __syncthreads();
#pragma unroll
        for (int k = 0; k < 8; ++k) {
            float a[8], bv[8];
            *(float4*)&a[0] = *(float4*)&As[k][rowBase];
            *(float4*)&a[4] = *(float4*)&As[k][rowBase + 4];
            *(float4*)&bv[0] = *(float4*)&Bs[k][colBase];
            *(float4*)&bv[4] = *(float4*)&Bs[k][colBase + 4];
#pragma unroll
            for (int i = 0; i < 8; ++i)
#pragma unroll
                for (int j = 0; j < 8; ++j) acc[i][j] += a[i] * bv[j];
        }
        __syncthreads();
    }
    for (int i = 0; i < 8; ++i) {
        float4* dst = (float4*)&Cc[(size_t)(tileM + rowBase + i) * HH + tileN + colBase];
        dst[0] = *(float4*)&acc[i][0];
        dst[1] = *(float4*)&acc[i][4];
    }
}

// ---------------------------------------------------------------------------
// E[c,f,h] = sum_o emb[c,f,o] * Wk[c,o,h]   (one block per (c,f))
__global__ void k_E(const float* __restrict__ emb, const float* __restrict__ Wk) {
    int c = blockIdx.y, f = blockIdx.x;
    const float* er = emb + ((size_t)c * FF + f) * HH;
    const float* W = Wk + (size_t)c * HH * HH;
    __shared__ float es[HH];
    for (int i = threadIdx.x; i < HH; i += 256) es[i] = er[i];
    __syncthreads();
    int h = threadIdx.x;
    float acc0 = 0.f, acc1 = 0.f, acc2 = 0.f, acc3 = 0.f;
#pragma unroll 4
    for (int o = 0; o < HH; ++o) {
        float e = es[o];
        const float* wr = W + (size_t)o * HH;
        acc0 += e * wr[h];
        acc1 += e * wr[h + 256];
        acc2 += e * wr[h + 512];
        acc3 += e * wr[h + 768];
    }
    float* outp = g_E + ((size_t)c * FF + f) * HH;
    outp[h] = acc0; outp[h + 256] = acc1; outp[h + 512] = acc2; outp[h + 768] = acc3;
}

// ---------------------------------------------------------------------------
// T[c] = hidden @ Mc[c]   (NN: A row-major [M,K], B row-major [K,N])
__global__ __launch_bounds__(256) void k_T(const float* __restrict__ hidden) {
    int c = blockIdx.z;
    const float* A = hidden;                            // [BB*SS, HH]
    const float* Bm = g_Mc + (size_t)c * HH * HH;       // [HH, HH]
    float* Tc = g_T + (size_t)c * BB * SS * HH;
    int tileM = blockIdx.y * 128, tileN = blockIdx.x * 128;
    __shared__ float As[8][128], Bs[8][128];
    int tid = threadIdx.x;
    int arow = tid >> 1, ak = (tid & 1) * 4;
    int bk = tid >> 5, bc = (tid & 31) * 4;
    int rowBase = (tid >> 4) * 8, colBase = (tid & 15) * 8;
    float acc[8][8] = {};
    for (int k0 = 0; k0 < HH; k0 += 8) {
        float4 av = *(const float4*)&A[(size_t)(tileM + arow) * HH + k0 + ak];
        As[ak + 0][arow] = av.x; As[ak + 1][arow] = av.y;
        As[ak + 2][arow] = av.z; As[ak + 3][arow] = av.w;
        *(float4*)&Bs[bk][bc] = *(const float4*)&Bm[(size_t)(k0 + bk) * HH + tileN + bc];
        __syncthreads();
#pragma unroll
        for (int k = 0; k < 8; ++k) {
            float a[8], bv[8];
            *(float4*)&a[0] = *(float4*)&As[k][rowBase];
            *(float4*)&a[4] = *(float4*)&As[k][rowBase + 4];
            *(float4*)&bv[0] = *(float4*)&Bs[k][colBase];
            *(float4*)&bv[4] = *(float4*)&Bs[k][colBase + 4];
#pragma unroll
            for (int i = 0; i < 8; ++i)
#pragma unroll
                for (int j = 0; j < 8; ++j) acc[i][j] += a[i] * bv[j];
        }
        __syncthreads();
    }
    for (int i = 0; i < 8; ++i) {
        float4* dst = (float4*)&Tc[(size_t)(tileM + rowBase + i) * HH + tileN + colBase];
        dst[0] = *(float4*)&acc[i][0];
        dst[1] = *(float4*)&acc[i][4];
    }
}

// ---------------------------------------------------------------------------
// out[b,c,i,j] = (rows(T[c,b]) ++ rows(E[c]))_i . hidden[b,j,:]  *  vsum[c,b,j]
// NT GEMM: A [2080,1024] K-major, B = hidden[b] [2048,1024] K-major.
__global__ __launch_bounds__(256) void k_main(const float* __restrict__ hidden,
                                              float* __restrict__ out) {
    int z = blockIdx.z;
    int c = z >> 4, b = z & 15;
    int tileN = blockIdx.x * 128, tileM = blockIdx.y * 128;
    const float* Bh = hidden + (size_t)b * SS * HH;
    const float* Tc = g_T + ((size_t)c * BB + b) * SS * HH;
    const float* Ec = g_E + (size_t)c * FF * HH;
    const float* vs = g_vsum + ((size_t)c * BB + b) * SS;
    __shared__ float As[8][128], Bs[8][128];
    int tid = threadIdx.x;
    int arow = tid >> 1, ak = (tid & 1) * 4;
    int rowBase = (tid >> 4) * 8, colBase = (tid & 15) * 8;
    float acc[8][8] = {};
    for (int k0 = 0; k0 < HH; k0 += 8) {
        int gi = tileM + arow;
        float4 av;
        if (gi < SS)       av = *(const float4*)&Tc[(size_t)gi * HH + k0 + ak];
        else if (gi < SF)  av = *(const float4*)&Ec[(size_t)(gi - SS) * HH + k0 + ak];
        else               av = make_float4(0.f, 0.f, 0.f, 0.f);
        As[ak + 0][arow] = av.x; As[ak + 1][arow] = av.y;
        As[ak + 2][arow] = av.z; As[ak + 3][arow] = av.w;
        float4 bv = *(const float4*)&Bh[(size_t)(tileN + arow) * HH + k0 + ak];
        Bs[ak + 0][arow] = bv.x; Bs[ak + 1][arow] = bv.y;
        Bs[ak + 2][arow] = bv.z; Bs[ak + 3][arow] = bv.w;
        __syncthreads();
#pragma unroll
        for (int k = 0; k < 8; ++k) {
            float a[8], bvv[8];
            *(float4*)&a[0] = *(float4*)&As[k][rowBase];
            *(float4*)&a[4] = *(float4*)&As[k][rowBase + 4];
            *(float4*)&bvv[0] = *(float4*)&Bs[k][colBase];
            *(float4*)&bvv[4] = *(float4*)&Bs[k][colBase + 4];
#pragma unroll
            for (int i = 0; i < 8; ++i)
#pragma unroll
                for (int j = 0; j < 8; ++j) acc[i][j] += a[i] * bvv[j];
        }
        __syncthreads();
    }
    float vsv[8];
#pragma unroll
    for (int j = 0; j < 8; ++j) vsv[j] = vs[tileN + colBase + j];
    for (int i = 0; i < 8; ++i) {
        int gi = tileM + rowBase + i;
        if (gi >= SF) continue;
        float4 o0, o1;
        o0.x = acc[i][0] * vsv[0]; o0.y = acc[i][1] * vsv[1];
        o0.z = acc[i][2] * vsv[2]; o0.w = acc[i][3] * vsv[3];
        o1.x = acc[i][4] * vsv[4]; o1.y = acc[i][5] * vsv[5];
        o1.z = acc[i][6] * vsv[6]; o1.w = acc[i][7] * vsv[7];
        size_t off = ((((size_t)b * CC + c) * SF) + gi) * SS + tileN + colBase;
        *(float4*)&out[off] = o0;
        *(float4*)&out[off + 4] = o1;
    }
}

// ---------------------------------------------------------------------------
extern "C" void kernel_launch(void* const* d_in, const int* in_sizes, int n_in,
                              void* d_out, int out_size) {
    const float* hidden = (const float*)d_in[0];  // [B,S,H]
    const float* emb    = (const float*)d_in[1];  // [C,F,H]
    const float* Wk     = (const float*)d_in[2];  // [C,H,H]
    const float* Wq     = (const float*)d_in[3];  // [C,H,H]
    const float* Wv     = (const float*)d_in[4];  // [C,H,H]
    float* out = (float*)d_out;                   // [B,C,S+F,S]

    k_wvsum<<<dim3(HH / 256, CC), 256>>>(Wv);
    k_vsum<<<(BB * SS) / 8, 256>>>(hidden);
    k_Mc<<<dim3(8, 8, CC), 256>>>(Wq, Wk);
    k_E<<<dim3(FF, CC), 256>>>(emb, Wk);
    k_T<<<dim3(HH / 128, (BB * SS) / 128, CC), 256>>>(hidden);
    k_main<<<dim3(SS / 128, (SF + 127) / 128, CC * BB), 256>>>(hidden, out);
}

// round 4
// speedup vs baseline: 2.1003x; 2.1003x over previous
#include <cuda_runtime.h>
#include <cuda_bf16.h>
#include <cstdint>

#define CC 2
#define FF 32
#define HH 1024
#define BB 16
#define SS 2048
#define SF (SS + FF)   // 2080
#define NC 16          // K chunks of 64
#define SRB 144        // smem row bytes (128 data + 16 pad): conflict-free ldmatrix
#define MATB (128 * SRB)
#define STGB (4 * MATB)
#define SMEM_TOTAL (2 * STGB)   // 147456

typedef __nv_bfloat16 bf16;

// ------------------------------ device scratch ----------------------------
__device__ bf16 g_hidH[(size_t)BB * SS * HH], g_hidL[(size_t)BB * SS * HH];
__device__ bf16 g_WqTH[(size_t)CC * HH * HH], g_WqTL[(size_t)CC * HH * HH];
__device__ bf16 g_WkTH[(size_t)CC * HH * HH], g_WkTL[(size_t)CC * HH * HH];
__device__ bf16 g_McTH[(size_t)CC * HH * HH], g_McTL[(size_t)CC * HH * HH];
__device__ bf16 g_embPH[(size_t)CC * 128 * HH], g_embPL[(size_t)CC * 128 * HH];  // rows 32-127 stay 0
__device__ bf16 g_EPH[(size_t)CC * 128 * HH], g_EPL[(size_t)CC * 128 * HH];
__device__ bf16 g_TH[(size_t)CC * BB * SS * HH], g_TL[(size_t)CC * BB * SS * HH];
__device__ float g_wvs[CC * HH];
__device__ float g_vsum[(size_t)CC * BB * SS];

// ------------------------------ helpers -----------------------------------
__device__ __forceinline__ uint32_t smem_to_u32(const void* p) {
    uint32_t a;
    asm("{ .reg .u64 t; cvta.to.shared.u64 t, %1; cvt.u32.u64 %0, t; }" : "=r"(a) : "l"(p));
    return a;
}
__device__ __forceinline__ void split2(float x, bf16& h, bf16& l) {
    h = __float2bfloat16(x);
    l = __float2bfloat16(x - __bfloat162float(h));
}
__device__ __forceinline__ uint32_t packbf(bf16 a, bf16 b) {
    return (uint32_t)__bfloat16_as_ushort(a) | ((uint32_t)__bfloat16_as_ushort(b) << 16);
}
__device__ __forceinline__ void ldsm4(uint32_t* r, uint32_t addr) {
    asm volatile("ldmatrix.sync.aligned.m8n8.x4.shared.b16 {%0,%1,%2,%3}, [%4];"
                 : "=r"(r[0]), "=r"(r[1]), "=r"(r[2]), "=r"(r[3]) : "r"(addr));
}
__device__ __forceinline__ void mma_bf16(float* c, const uint32_t* a, uint32_t b0, uint32_t b1) {
    asm volatile(
        "mma.sync.aligned.m16n8k16.row.col.f32.bf16.bf16.f32 "
        "{%0,%1,%2,%3},{%4,%5,%6,%7},{%8,%9},{%0,%1,%2,%3};"
        : "+f"(c[0]), "+f"(c[1]), "+f"(c[2]), "+f"(c[3])
        : "r"(a[0]), "r"(a[1]), "r"(a[2]), "r"(a[3]), "r"(b0), "r"(b1));
}
#define CPA(s, g) asm volatile("cp.async.cg.shared.global [%0], [%1], 16;" :: "r"(s), "l"(g))
#define CPA_COMMIT() asm volatile("cp.async.commit_group;" ::: "memory")
#define CPA_WAIT1() asm volatile("cp.async.wait_group 1;" ::: "memory")
#define CPA_WAIT0() asm volatile("cp.async.wait_group 0;" ::: "memory")

// ------------------------------ prep kernels ------------------------------
__global__ void k_wvsum(const float* __restrict__ Wv) {
    int c = blockIdx.y;
    int h = blockIdx.x * 256 + threadIdx.x;
    const float* W = Wv + (size_t)c * HH * HH;
    float a = 0.f;
#pragma unroll 8
    for (int o = 0; o < HH; ++o) a += W[(size_t)o * HH + h];
    g_wvs[c * HH + h] = a;
}

__global__ void k_vsum(const float* __restrict__ hidden) {
    int w = (blockIdx.x * blockDim.x + threadIdx.x) >> 5;
    int lane = threadIdx.x & 31;
    if (w >= BB * SS) return;
    const float* hr = hidden + (size_t)w * HH;
    float a0 = 0.f, a1 = 0.f;
#pragma unroll 4
    for (int i = lane; i < HH; i += 32) {
        float hv = hr[i];
        a0 += hv * g_wvs[i];
        a1 += hv * g_wvs[HH + i];
    }
#pragma unroll
    for (int off = 16; off; off >>= 1) {
        a0 += __shfl_down_sync(0xFFFFFFFFu, a0, off);
        a1 += __shfl_down_sync(0xFFFFFFFFu, a1, off);
    }
    if (lane == 0) {
        g_vsum[w] = a0;
        g_vsum[(size_t)BB * SS + w] = a1;
    }
}

__global__ void k_cvt_hidden(const float* __restrict__ in) {
    size_t i = (size_t)blockIdx.x * blockDim.x + threadIdx.x;
    float4 v = ((const float4*)in)[i];
    bf16 h0, l0, h1, l1, h2, l2, h3, l3;
    split2(v.x, h0, l0); split2(v.y, h1, l1); split2(v.z, h2, l2); split2(v.w, h3, l3);
    ((uint32_t*)g_hidH)[2 * i] = packbf(h0, h1);
    ((uint32_t*)g_hidH)[2 * i + 1] = packbf(h2, h3);
    ((uint32_t*)g_hidL)[2 * i] = packbf(l0, l1);
    ((uint32_t*)g_hidL)[2 * i + 1] = packbf(l2, l3);
}

__global__ void k_cvt_emb(const float* __restrict__ emb) {
    int i = blockIdx.x * blockDim.x + threadIdx.x;
    int e = i * 4;
    int c = e / (FF * HH);
    int rem = e - c * FF * HH;
    int f = rem / HH, h = rem - f * HH;
    float4 v = ((const float4*)emb)[i];
    bf16 h0, l0, h1, l1, h2, l2, h3, l3;
    split2(v.x, h0, l0); split2(v.y, h1, l1); split2(v.z, h2, l2); split2(v.w, h3, l3);
    size_t o = ((size_t)c * 128 + f) * HH + h;
    *(uint32_t*)&g_embPH[o] = packbf(h0, h1);
    *(uint32_t*)&g_embPH[o + 2] = packbf(h2, h3);
    *(uint32_t*)&g_embPL[o] = packbf(l0, l1);
    *(uint32_t*)&g_embPL[o + 2] = packbf(l2, l3);
}

template <int W>
__global__ void k_tsplit(const float* __restrict__ in) {
    __shared__ float t[32][33];
    int c = blockIdx.z;
    const float* I = in + (size_t)c * HH * HH;
    bf16* OH = (W == 0 ? g_WqTH : g_WkTH) + (size_t)c * HH * HH;
    bf16* OL = (W == 0 ? g_WqTL : g_WkTL) + (size_t)c * HH * HH;
    int x = blockIdx.x * 32 + threadIdx.x;
#pragma unroll
    for (int i = threadIdx.y; i < 32; i += 8)
        t[i][threadIdx.x] = I[(size_t)(blockIdx.y * 32 + i) * HH + x];
    __syncthreads();
    int ox = blockIdx.y * 32 + threadIdx.x;
#pragma unroll
    for (int i = threadIdx.y; i < 32; i += 8) {
        float v = t[threadIdx.x][i];
        bf16 h, l;
        split2(v, h, l);
        size_t o = (size_t)(blockIdx.x * 32 + i) * HH + ox;
        OH[o] = h;
        OL[o] = l;
    }
}

// ------------------------------ GEMM core ---------------------------------
// C[128,128] = (Ahi+Alo)[128,K] . (Bhi+Blo)[128,K]^T  via 3 bf16 mma splits.
// MODE 0: McT   1: E   2: T   3: main (x vsum -> out)
template <int MODE>
__global__ void __launch_bounds__(256, 1) k_gemm(float* __restrict__ out) {
    extern __shared__ __align__(128) char smem[];
    const uint32_t sb = smem_to_u32(smem);
    const int tid = threadIdx.x, wid = tid >> 5, lane = tid & 31;
    const int bx = blockIdx.x, by = blockIdx.y, bz = blockIdx.z;

    const bf16 *AH, *AL, *BH, *BL;
    if (MODE == 0) {
        size_t cb = (size_t)bz * HH * HH;
        AH = g_WkTH + cb + (size_t)by * 128 * HH; AL = g_WkTL + cb + (size_t)by * 128 * HH;
        BH = g_WqTH + cb + (size_t)bx * 128 * HH; BL = g_WqTL + cb + (size_t)bx * 128 * HH;
    } else if (MODE == 1) {
        AH = g_embPH + (size_t)bz * 128 * HH; AL = g_embPL + (size_t)bz * 128 * HH;
        size_t cb = (size_t)bz * HH * HH;
        BH = g_WkTH + cb + (size_t)bx * 128 * HH; BL = g_WkTL + cb + (size_t)bx * 128 * HH;
    } else if (MODE == 2) {
        AH = g_hidH + (size_t)by * 128 * HH; AL = g_hidL + (size_t)by * 128 * HH;
        size_t cb = (size_t)bz * HH * HH;
        BH = g_McTH + cb + (size_t)bx * 128 * HH; BL = g_McTL + cb + (size_t)bx * 128 * HH;
    } else {
        int c = bz >> 4, b = bz & 15;
        if (by < 16) {
            size_t ro = ((size_t)c * BB * SS + (size_t)b * SS + (size_t)by * 128) * HH;
            AH = g_TH + ro; AL = g_TL + ro;
        } else {
            AH = g_EPH + (size_t)c * 128 * HH; AL = g_EPL + (size_t)c * 128 * HH;
        }
        size_t bo = ((size_t)b * SS + (size_t)bx * 128) * HH;
        BH = g_hidH + bo; BL = g_hidL + bo;
    }
    const bf16* srcs[4] = {AH, AL, BH, BL};

    // loader mapping: row = tid>>1 (128 rows), half = tid&1 (64B each), 4x16B units
    const int lrow = tid >> 1, lhalf = tid & 1;
    const uint32_t sRowOff = (uint32_t)(lrow * SRB + lhalf * 64);
    const size_t gRowOff = (size_t)lrow * HH + lhalf * 32;

    // compute mapping
    const int wm = wid >> 2, wn = wid & 3;
    const uint32_t aOff = (uint32_t)((wm * 64 + (lane & 15)) * SRB + ((lane >> 4) << 4));
    const uint32_t bOff = (uint32_t)((wn * 32 + (lane & 7) + ((lane >> 4) & 1) * 8) * SRB +
                                     (((lane >> 3) & 1) << 4));

    float acc[4][4][4] = {};

    // prologue: chunk 0 -> stage 0
#pragma unroll
    for (int mi = 0; mi < 4; mi++) {
        uint32_t sa = sb + mi * MATB + sRowOff;
        const bf16* gp = srcs[mi] + gRowOff;
#pragma unroll
        for (int i = 0; i < 4; i++) CPA(sa + i * 16, gp + i * 8);
    }
    CPA_COMMIT();

    for (int ck = 0; ck < NC; ck++) {
        if (ck + 1 < NC) {
            const int stg = (ck + 1) & 1;
            const int kof = (ck + 1) * 64;
#pragma unroll
            for (int mi = 0; mi < 4; mi++) {
                uint32_t sa = sb + stg * STGB + mi * MATB + sRowOff;
                const bf16* gp = srcs[mi] + gRowOff + kof;
#pragma unroll
                for (int i = 0; i < 4; i++) CPA(sa + i * 16, gp + i * 8);
            }
            CPA_COMMIT();
            CPA_WAIT1();
        } else {
            CPA_WAIT0();
        }
        __syncthreads();

        const uint32_t base = sb + (ck & 1) * STGB;
        const uint32_t pAH = base + aOff, pAL = base + MATB + aOff;
        const uint32_t pBH = base + 2 * MATB + bOff, pBL = base + 3 * MATB + bOff;
#pragma unroll
        for (int ka = 0; ka < 4; ka++) {
            uint32_t A[4][4], Bh[2][4], Bl[2][4];
#pragma unroll
            for (int m = 0; m < 4; m++) ldsm4(A[m], pAH + m * (16 * SRB) + ka * 32);
#pragma unroll
            for (int nb = 0; nb < 2; nb++) ldsm4(Bh[nb], pBH + nb * (16 * SRB) + ka * 32);
#pragma unroll
            for (int m = 0; m < 4; m++)
#pragma unroll
                for (int n8 = 0; n8 < 4; n8++)
                    mma_bf16(acc[m][n8], A[m], Bh[n8 >> 1][(n8 & 1) * 2], Bh[n8 >> 1][(n8 & 1) * 2 + 1]);
#pragma unroll
            for (int nb = 0; nb < 2; nb++) ldsm4(Bl[nb], pBL + nb * (16 * SRB) + ka * 32);
#pragma unroll
            for (int m = 0; m < 4; m++)
#pragma unroll
                for (int n8 = 0; n8 < 4; n8++)
                    mma_bf16(acc[m][n8], A[m], Bl[n8 >> 1][(n8 & 1) * 2], Bl[n8 >> 1][(n8 & 1) * 2 + 1]);
#pragma unroll
            for (int m = 0; m < 4; m++) ldsm4(A[m], pAL + m * (16 * SRB) + ka * 32);
#pragma unroll
            for (int m = 0; m < 4; m++)
#pragma unroll
                for (int n8 = 0; n8 < 4; n8++)
                    mma_bf16(acc[m][n8], A[m], Bh[n8 >> 1][(n8 & 1) * 2], Bh[n8 >> 1][(n8 & 1) * 2 + 1]);
        }
        __syncthreads();
    }

    // ------------------------------ epilogue --------------------------------
    const int rBase = wm * 64 + (lane >> 2);
    const int cBase = wn * 32 + (lane & 3) * 2;
    if (MODE == 3) {
        int c = bz >> 4, b = bz & 15;
        const float* vsp = g_vsum + ((size_t)c * BB + b) * SS + bx * 128;
        float* ob = out + ((size_t)b * CC + c) * SF * SS;
#pragma unroll
        for (int m = 0; m < 4; m++) {
            int r0 = by * 128 + m * 16 + rBase;
#pragma unroll
            for (int n8 = 0; n8 < 4; n8++) {
                int cc = cBase + n8 * 8;
                float2 vs = *(const float2*)(vsp + cc);
                size_t col = (size_t)bx * 128 + cc;
                if (r0 < SF) {
                    float2 o;
                    o.x = acc[m][n8][0] * vs.x;
                    o.y = acc[m][n8][1] * vs.y;
                    *(float2*)(ob + (size_t)r0 * SS + col) = o;
                }
                if (r0 + 8 < SF) {
                    float2 o;
                    o.x = acc[m][n8][2] * vs.x;
                    o.y = acc[m][n8][3] * vs.y;
                    *(float2*)(ob + (size_t)(r0 + 8) * SS + col) = o;
                }
            }
        }
    } else {
        bf16 *OH, *OL;
        size_t rowB;
        if (MODE == 0) {
            OH = g_McTH; OL = g_McTL;
            rowB = (size_t)bz * HH * HH + (size_t)(by * 128) * HH;
        } else if (MODE == 1) {
            OH = g_EPH; OL = g_EPL;
            rowB = (size_t)bz * 128 * HH;
        } else {
            OH = g_TH; OL = g_TL;
            rowB = ((size_t)bz * BB * SS + (size_t)by * 128) * HH;
        }
#pragma unroll
        for (int m = 0; m < 4; m++) {
            int r0 = m * 16 + rBase;
#pragma unroll
            for (int n8 = 0; n8 < 4; n8++) {
                int cc = bx * 128 + cBase + n8 * 8;
                bf16 h0, l0, h1, l1;
                split2(acc[m][n8][0], h0, l0);
                split2(acc[m][n8][1], h1, l1);
                *(uint32_t*)&OH[rowB + (size_t)r0 * HH + cc] = packbf(h0, h1);
                *(uint32_t*)&OL[rowB + (size_t)r0 * HH + cc] = packbf(l0, l1);
                split2(acc[m][n8][2], h0, l0);
                split2(acc[m][n8][3], h1, l1);
                *(uint32_t*)&OH[rowB + (size_t)(r0 + 8) * HH + cc] = packbf(h0, h1);
                *(uint32_t*)&OL[rowB + (size_t)(r0 + 8) * HH + cc] = packbf(l0, l1);
            }
        }
    }
}

// ------------------------------ launch ------------------------------------
extern "C" void kernel_launch(void* const* d_in, const int* in_sizes, int n_in,
                              void* d_out, int out_size) {
    const float* hidden = (const float*)d_in[0];
    const float* emb    = (const float*)d_in[1];
    const float* Wk     = (const float*)d_in[2];
    const float* Wq     = (const float*)d_in[3];
    const float* Wv     = (const float*)d_in[4];
    float* out = (float*)d_out;

    cudaFuncSetAttribute(k_gemm<0>, cudaFuncAttributeMaxDynamicSharedMemorySize, SMEM_TOTAL);
    cudaFuncSetAttribute(k_gemm<1>, cudaFuncAttributeMaxDynamicSharedMemorySize, SMEM_TOTAL);
    cudaFuncSetAttribute(k_gemm<2>, cudaFuncAttributeMaxDynamicSharedMemorySize, SMEM_TOTAL);
    cudaFuncSetAttribute(k_gemm<3>, cudaFuncAttributeMaxDynamicSharedMemorySize, SMEM_TOTAL);

    k_wvsum<<<dim3(HH / 256, CC), 256>>>(Wv);
    k_vsum<<<(BB * SS) / 8, 256>>>(hidden);
    k_cvt_hidden<<<((size_t)BB * SS * HH / 4) / 256, 256>>>(hidden);
    k_cvt_emb<<<(CC * FF * HH / 4) / 256, 256>>>(emb);
    k_tsplit<0><<<dim3(32, 32, CC), dim3(32, 8)>>>(Wq);
    k_tsplit<1><<<dim3(32, 32, CC), dim3(32, 8)>>>(Wk);

    k_gemm<0><<<dim3(8, 8, CC), 256, SMEM_TOTAL>>>(nullptr);     // McT
    k_gemm<1><<<dim3(8, 1, CC), 256, SMEM_TOTAL>>>(nullptr);     // E
    k_gemm<2><<<dim3(8, 256, CC), 256, SMEM_TOTAL>>>(nullptr);   // T
    k_gemm<3><<<dim3(16, 17, CC * BB), 256, SMEM_TOTAL>>>(out);  // scores
}

// round 5
// speedup vs baseline: 2.1210x; 1.0098x over previous
#include <cuda_runtime.h>
#include <cuda_bf16.h>
#include <cstdint>

#define CC 2
#define FF 32
#define HH 1024
#define BB 16
#define SS 2048
#define SF (SS + FF)   // 2080
#define NC 16          // K chunks of 64
#define SRB 144        // smem row bytes (128 data + 16 pad)
// stage layout: Ahi[128] Alo[128] Bhi[256] Blo[256] rows
#define OFF_AH 0
#define OFF_AL (128 * SRB)
#define OFF_BH (256 * SRB)
#define OFF_BL (512 * SRB)
#define STGB (768 * SRB)            // 110592
#define SMEM_TOTAL (2 * STGB)       // 221184

typedef __nv_bfloat16 bf16;

// ------------------------------ device scratch ----------------------------
__device__ bf16 g_hidH[(size_t)BB * SS * HH], g_hidL[(size_t)BB * SS * HH];
__device__ bf16 g_WqTH[(size_t)CC * HH * HH], g_WqTL[(size_t)CC * HH * HH];
__device__ bf16 g_WkTH[(size_t)CC * HH * HH], g_WkTL[(size_t)CC * HH * HH];
__device__ bf16 g_McTH[(size_t)CC * HH * HH], g_McTL[(size_t)CC * HH * HH];
__device__ bf16 g_embPH[(size_t)CC * 128 * HH], g_embPL[(size_t)CC * 128 * HH];  // rows>=32 stay 0
__device__ bf16 g_EPH[(size_t)CC * 128 * HH], g_EPL[(size_t)CC * 128 * HH];
__device__ bf16 g_TH[(size_t)CC * BB * SS * HH], g_TL[(size_t)CC * BB * SS * HH];
__device__ float g_wvs[CC * HH];
__device__ float g_vsum[(size_t)CC * BB * SS];

// ------------------------------ helpers -----------------------------------
__device__ __forceinline__ uint32_t smem_to_u32(const void* p) {
    uint32_t a;
    asm("{ .reg .u64 t; cvta.to.shared.u64 t, %1; cvt.u32.u64 %0, t; }" : "=r"(a) : "l"(p));
    return a;
}
__device__ __forceinline__ void split2(float x, bf16& h, bf16& l) {
    h = __float2bfloat16(x);
    l = __float2bfloat16(x - __bfloat162float(h));
}
__device__ __forceinline__ uint32_t packbf(bf16 a, bf16 b) {
    return (uint32_t)__bfloat16_as_ushort(a) | ((uint32_t)__bfloat16_as_ushort(b) << 16);
}
__device__ __forceinline__ void ldsm4(uint32_t* r, uint32_t addr) {
    asm volatile("ldmatrix.sync.aligned.m8n8.x4.shared.b16 {%0,%1,%2,%3}, [%4];"
                 : "=r"(r[0]), "=r"(r[1]), "=r"(r[2]), "=r"(r[3]) : "r"(addr));
}
__device__ __forceinline__ void mma_bf16(float* c, const uint32_t* a, uint32_t b0, uint32_t b1) {
    asm volatile(
        "mma.sync.aligned.m16n8k16.row.col.f32.bf16.bf16.f32 "
        "{%0,%1,%2,%3},{%4,%5,%6,%7},{%8,%9},{%0,%1,%2,%3};"
        : "+f"(c[0]), "+f"(c[1]), "+f"(c[2]), "+f"(c[3])
        : "r"(a[0]), "r"(a[1]), "r"(a[2]), "r"(a[3]), "r"(b0), "r"(b1));
}
#define CPA(s, g) asm volatile("cp.async.cg.shared.global [%0], [%1], 16;" :: "r"(s), "l"(g))
#define CPA_COMMIT() asm volatile("cp.async.commit_group;" ::: "memory")
#define CPA_WAIT1() asm volatile("cp.async.wait_group 1;" ::: "memory")
#define CPA_WAIT0() asm volatile("cp.async.wait_group 0;" ::: "memory")

// ------------------------------ prep kernels ------------------------------
#define HID_BLOCKS 32768   // (BB*SS*HH/4)/256
__global__ void k_cvt(const float* __restrict__ hidden, const float* __restrict__ emb) {
    int bid = blockIdx.x;
    if (bid < HID_BLOCKS) {
        size_t i = (size_t)bid * 256 + threadIdx.x;
        float4 v = ((const float4*)hidden)[i];
        bf16 h0, l0, h1, l1, h2, l2, h3, l3;
        split2(v.x, h0, l0); split2(v.y, h1, l1); split2(v.z, h2, l2); split2(v.w, h3, l3);
        ((uint32_t*)g_hidH)[2 * i] = packbf(h0, h1);
        ((uint32_t*)g_hidH)[2 * i + 1] = packbf(h2, h3);
        ((uint32_t*)g_hidL)[2 * i] = packbf(l0, l1);
        ((uint32_t*)g_hidL)[2 * i + 1] = packbf(l2, l3);
    } else {
        int i = (bid - HID_BLOCKS) * 256 + threadIdx.x;  // float4 index into emb
        int e = i * 4;
        int c = e / (FF * HH);
        int rem = e - c * FF * HH;
        int f = rem / HH, h = rem - f * HH;
        float4 v = ((const float4*)emb)[i];
        bf16 h0, l0, h1, l1, h2, l2, h3, l3;
        split2(v.x, h0, l0); split2(v.y, h1, l1); split2(v.z, h2, l2); split2(v.w, h3, l3);
        size_t o = ((size_t)c * 128 + f) * HH + h;
        *(uint32_t*)&g_embPH[o] = packbf(h0, h1);
        *(uint32_t*)&g_embPH[o + 2] = packbf(h2, h3);
        *(uint32_t*)&g_embPL[o] = packbf(l0, l1);
        *(uint32_t*)&g_embPL[o + 2] = packbf(l2, l3);
    }
}

__global__ void k_tsplit_both(const float* __restrict__ Wq, const float* __restrict__ Wk) {
    __shared__ float t[32][33];
    int z = blockIdx.z;
    int c = z >> 1, W = z & 1;
    const float* I = (W == 0 ? Wq : Wk) + (size_t)c * HH * HH;
    bf16* OH = (W == 0 ? g_WqTH : g_WkTH) + (size_t)c * HH * HH;
    bf16* OL = (W == 0 ? g_WqTL : g_WkTL) + (size_t)c * HH * HH;
    int x = blockIdx.x * 32 + threadIdx.x;
#pragma unroll
    for (int i = threadIdx.y; i < 32; i += 8)
        t[i][threadIdx.x] = I[(size_t)(blockIdx.y * 32 + i) * HH + x];
    __syncthreads();
    int ox = blockIdx.y * 32 + threadIdx.x;
#pragma unroll
    for (int i = threadIdx.y; i < 32; i += 8) {
        float v = t[threadIdx.x][i];
        bf16 h, l;
        split2(v, h, l);
        size_t o = (size_t)(blockIdx.x * 32 + i) * HH + ox;
        OH[o] = h;
        OL[o] = l;
    }
}

__global__ void k_wvsum(const float* __restrict__ Wv) {
    int c = blockIdx.y;
    int h = blockIdx.x * 256 + threadIdx.x;
    const float* W = Wv + (size_t)c * HH * HH;
    float a = 0.f;
#pragma unroll 8
    for (int o = 0; o < HH; ++o) a += W[(size_t)o * HH + h];
    g_wvs[c * HH + h] = a;
}

__global__ void k_vsum(const float* __restrict__ hidden) {
    int w = (blockIdx.x * blockDim.x + threadIdx.x) >> 5;
    int lane = threadIdx.x & 31;
    if (w >= BB * SS) return;
    const float* hr = hidden + (size_t)w * HH;
    float a0 = 0.f, a1 = 0.f;
#pragma unroll 4
    for (int i = lane; i < HH; i += 32) {
        float hv = hr[i];
        a0 += hv * g_wvs[i];
        a1 += hv * g_wvs[HH + i];
    }
#pragma unroll
    for (int off = 16; off; off >>= 1) {
        a0 += __shfl_down_sync(0xFFFFFFFFu, a0, off);
        a1 += __shfl_down_sync(0xFFFFFFFFu, a1, off);
    }
    if (lane == 0) {
        g_vsum[w] = a0;
        g_vsum[(size_t)BB * SS + w] = a1;
    }
}

// ------------------------------ GEMM core ---------------------------------
// C[128,256] = (Ahi+Alo)[128,K] . (Bhi+Blo)[256,K]^T  via 3 bf16 mma splits.
// MODE 0: McT   1: E   2: T   3: main (x vsum -> out)
template <int MODE>
__global__ void __launch_bounds__(256, 1) k_gemm(float* __restrict__ out) {
    extern __shared__ __align__(128) char smem[];
    const uint32_t sb = smem_to_u32(smem);
    const int tid = threadIdx.x, wid = tid >> 5, lane = tid & 31;
    const int bx = blockIdx.x, by = blockIdx.y, bz = blockIdx.z;

    const bf16 *AH, *AL, *BH, *BL;
    if (MODE == 0) {
        size_t cb = (size_t)bz * HH * HH;
        AH = g_WkTH + cb + (size_t)by * 128 * HH; AL = g_WkTL + cb + (size_t)by * 128 * HH;
        BH = g_WqTH + cb + (size_t)bx * 256 * HH; BL = g_WqTL + cb + (size_t)bx * 256 * HH;
    } else if (MODE == 1) {
        AH = g_embPH + (size_t)bz * 128 * HH; AL = g_embPL + (size_t)bz * 128 * HH;
        size_t cb = (size_t)bz * HH * HH;
        BH = g_WkTH + cb + (size_t)bx * 256 * HH; BL = g_WkTL + cb + (size_t)bx * 256 * HH;
    } else if (MODE == 2) {
        AH = g_hidH + (size_t)by * 128 * HH; AL = g_hidL + (size_t)by * 128 * HH;
        size_t cb = (size_t)bz * HH * HH;
        BH = g_McTH + cb + (size_t)bx * 256 * HH; BL = g_McTL + cb + (size_t)bx * 256 * HH;
    } else {
        int c = bz >> 4, b = bz & 15;
        if (by < 16) {
            size_t ro = ((size_t)c * BB * SS + (size_t)b * SS + (size_t)by * 128) * HH;
            AH = g_TH + ro; AL = g_TL + ro;
        } else {
            AH = g_EPH + (size_t)c * 128 * HH; AL = g_EPL + (size_t)c * 128 * HH;
        }
        size_t bo = ((size_t)b * SS + (size_t)bx * 256) * HH;
        BH = g_hidH + bo; BL = g_hidL + bo;
    }

    // loader mapping
    const int lrow = tid >> 1, lhalf = tid & 1;                 // A: 2 thr/row
    const uint32_t sAOff = (uint32_t)(lrow * SRB + lhalf * 64);
    const size_t gAOff = (size_t)lrow * HH + lhalf * 32;
    const uint32_t sBOff = (uint32_t)(tid * SRB);               // B: 1 thr/row
    const size_t gBOff = (size_t)tid * HH;

    // compute mapping: warp tile 64x64
    const int wm = wid >> 2, wn = wid & 3;
    const uint32_t aOff = (uint32_t)((wm * 64 + (lane & 15)) * SRB + ((lane >> 4) << 4));
    const uint32_t bOff = (uint32_t)((wn * 64 + (lane & 7) + ((lane >> 4) & 1) * 8) * SRB +
                                     (((lane >> 3) & 1) << 4));

    float acc[4][8][4] = {};

    // prologue: chunk 0 -> stage 0
    {
#pragma unroll
        for (int i = 0; i < 4; i++) {
            CPA(sb + OFF_AH + sAOff + i * 16, AH + gAOff + i * 8);
            CPA(sb + OFF_AL + sAOff + i * 16, AL + gAOff + i * 8);
        }
#pragma unroll
        for (int i = 0; i < 8; i++) {
            CPA(sb + OFF_BH + sBOff + i * 16, BH + gBOff + i * 8);
            CPA(sb + OFF_BL + sBOff + i * 16, BL + gBOff + i * 8);
        }
        CPA_COMMIT();
    }

    for (int ck = 0; ck < NC; ck++) {
        if (ck + 1 < NC) {
            const uint32_t stg = sb + ((ck + 1) & 1) * STGB;
            const int kof = (ck + 1) * 64;
#pragma unroll
            for (int i = 0; i < 4; i++) {
                CPA(stg + OFF_AH + sAOff + i * 16, AH + gAOff + kof + i * 8);
                CPA(stg + OFF_AL + sAOff + i * 16, AL + gAOff + kof + i * 8);
            }
#pragma unroll
            for (int i = 0; i < 8; i++) {
                CPA(stg + OFF_BH + sBOff + i * 16, BH + gBOff + kof + i * 8);
                CPA(stg + OFF_BL + sBOff + i * 16, BL + gBOff + kof + i * 8);
            }
            CPA_COMMIT();
            CPA_WAIT1();
        } else {
            CPA_WAIT0();
        }
        __syncthreads();

        const uint32_t base = sb + (ck & 1) * STGB;
        const uint32_t pAH = base + OFF_AH + aOff, pAL = base + OFF_AL + aOff;
        const uint32_t pBH = base + OFF_BH + bOff, pBL = base + OFF_BL + bOff;
#pragma unroll
        for (int ka = 0; ka < 4; ka++) {
            uint32_t A[4][4], Bh[4][4], Bl[4][4];
#pragma unroll
            for (int m = 0; m < 4; m++) ldsm4(A[m], pAH + m * (16 * SRB) + ka * 32);
#pragma unroll
            for (int nb = 0; nb < 4; nb++) ldsm4(Bh[nb], pBH + nb * (16 * SRB) + ka * 32);
#pragma unroll
            for (int m = 0; m < 4; m++)
#pragma unroll
                for (int n8 = 0; n8 < 8; n8++)
                    mma_bf16(acc[m][n8], A[m], Bh[n8 >> 1][(n8 & 1) * 2], Bh[n8 >> 1][(n8 & 1) * 2 + 1]);
#pragma unroll
            for (int nb = 0; nb < 4; nb++) ldsm4(Bl[nb], pBL + nb * (16 * SRB) + ka * 32);
#pragma unroll
            for (int m = 0; m < 4; m++)
#pragma unroll
                for (int n8 = 0; n8 < 8; n8++)
                    mma_bf16(acc[m][n8], A[m], Bl[n8 >> 1][(n8 & 1) * 2], Bl[n8 >> 1][(n8 & 1) * 2 + 1]);
#pragma unroll
            for (int m = 0; m < 4; m++) ldsm4(A[m], pAL + m * (16 * SRB) + ka * 32);
#pragma unroll
            for (int m = 0; m < 4; m++)
#pragma unroll
                for (int n8 = 0; n8 < 8; n8++)
                    mma_bf16(acc[m][n8], A[m], Bh[n8 >> 1][(n8 & 1) * 2], Bh[n8 >> 1][(n8 & 1) * 2 + 1]);
        }
        __syncthreads();
    }

    // ------------------------------ epilogue --------------------------------
    const int rBase = wm * 64 + (lane >> 2);
    const int cBase = wn * 64 + (lane & 3) * 2;
    if (MODE == 3) {
        int c = bz >> 4, b = bz & 15;
        const float* vsp = g_vsum + ((size_t)c * BB + b) * SS + bx * 256;
        float* ob = out + ((size_t)b * CC + c) * SF * SS;
#pragma unroll
        for (int m = 0; m < 4; m++) {
            int r0 = by * 128 + m * 16 + rBase;
#pragma unroll
            for (int n8 = 0; n8 < 8; n8++) {
                int cc = cBase + n8 * 8;
                float2 vs = *(const float2*)(vsp + cc);
                size_t col = (size_t)bx * 256 + cc;
                if (r0 < SF) {
                    float2 o;
                    o.x = acc[m][n8][0] * vs.x;
                    o.y = acc[m][n8][1] * vs.y;
                    *(float2*)(ob + (size_t)r0 * SS + col) = o;
                }
                if (r0 + 8 < SF) {
                    float2 o;
                    o.x = acc[m][n8][2] * vs.x;
                    o.y = acc[m][n8][3] * vs.y;
                    *(float2*)(ob + (size_t)(r0 + 8) * SS + col) = o;
                }
            }
        }
    } else {
        bf16 *OH, *OL;
        size_t rowB;
        if (MODE == 0) {
            OH = g_McTH; OL = g_McTL;
            rowB = (size_t)bz * HH * HH + (size_t)(by * 128) * HH;
        } else if (MODE == 1) {
            OH = g_EPH; OL = g_EPL;
            rowB = (size_t)bz * 128 * HH;
        } else {
            OH = g_TH; OL = g_TL;
            rowB = ((size_t)bz * BB * SS + (size_t)by * 128) * HH;
        }
#pragma unroll
        for (int m = 0; m < 4; m++) {
            int r0 = m * 16 + rBase;
#pragma unroll
            for (int n8 = 0; n8 < 8; n8++) {
                int cc = bx * 256 + cBase + n8 * 8;
                bf16 h0, l0, h1, l1;
                split2(acc[m][n8][0], h0, l0);
                split2(acc[m][n8][1], h1, l1);
                *(uint32_t*)&OH[rowB + (size_t)r0 * HH + cc] = packbf(h0, h1);
                *(uint32_t*)&OL[rowB + (size_t)r0 * HH + cc] = packbf(l0, l1);
                split2(acc[m][n8][2], h0, l0);
                split2(acc[m][n8][3], h1, l1);
                *(uint32_t*)&OH[rowB + (size_t)(r0 + 8) * HH + cc] = packbf(h0, h1);
                *(uint32_t*)&OL[rowB + (size_t)(r0 + 8) * HH + cc] = packbf(l0, l1);
            }
        }
    }
}

// ------------------------------ launch ------------------------------------
extern "C" void kernel_launch(void* const* d_in, const int* in_sizes, int n_in,
                              void* d_out, int out_size) {
    const float* hidden = (const float*)d_in[0];
    const float* emb    = (const float*)d_in[1];
    const float* Wk     = (const float*)d_in[2];
    const float* Wq     = (const float*)d_in[3];
    const float* Wv     = (const float*)d_in[4];
    float* out = (float*)d_out;

    cudaFuncSetAttribute(k_gemm<0>, cudaFuncAttributeMaxDynamicSharedMemorySize, SMEM_TOTAL);
    cudaFuncSetAttribute(k_gemm<1>, cudaFuncAttributeMaxDynamicSharedMemorySize, SMEM_TOTAL);
    cudaFuncSetAttribute(k_gemm<2>, cudaFuncAttributeMaxDynamicSharedMemorySize, SMEM_TOTAL);
    cudaFuncSetAttribute(k_gemm<3>, cudaFuncAttributeMaxDynamicSharedMemorySize, SMEM_TOTAL);

    // launch order chosen so the 4th launch (ncu capture slot) is k_gemm<2>
    k_cvt<<<HID_BLOCKS + 64, 256>>>(hidden, emb);                  // 1
    k_tsplit_both<<<dim3(32, 32, 2 * CC), dim3(32, 8)>>>(Wq, Wk);  // 2
    k_gemm<0><<<dim3(4, 8, CC), 256, SMEM_TOTAL>>>(nullptr);       // 3: McT
    k_gemm<2><<<dim3(4, 256, CC), 256, SMEM_TOTAL>>>(nullptr);     // 4: T  <- ncu
    k_gemm<1><<<dim3(4, 1, CC), 256, SMEM_TOTAL>>>(nullptr);       // 5: E
    k_wvsum<<<dim3(HH / 256, CC), 256>>>(Wv);                      // 6
    k_vsum<<<(BB * SS) / 8, 256>>>(hidden);                        // 7
    k_gemm<3><<<dim3(8, 17, CC * BB), 256, SMEM_TOTAL>>>(out);     // 8: scores
}

// round 6
// speedup vs baseline: 2.1228x; 1.0008x over previous
#include <cuda_runtime.h>
#include <cuda_bf16.h>
#include <cstdint>

#define CC 2
#define FF 32
#define HH 1024
#define BB 16
#define SS 2048
#define SF (SS + FF)   // 2080
#define NC 16          // K chunks of 64
#define SRB 144        // smem row bytes (128 data + 16 pad)
// stage layout: Ahi[128] Alo[128] Bhi[256] Blo[256] rows
#define OFF_AH 0
#define OFF_AL (128 * SRB)
#define OFF_BH (256 * SRB)
#define OFF_BL (512 * SRB)
#define STGB (768 * SRB)            // 110592
#define SMEM_TOTAL (2 * STGB)       // 221184

typedef __nv_bfloat16 bf16;

// ------------------------------ device scratch ----------------------------
__device__ bf16 g_hidH[(size_t)BB * SS * HH], g_hidL[(size_t)BB * SS * HH];
__device__ bf16 g_WqTH[(size_t)CC * HH * HH], g_WqTL[(size_t)CC * HH * HH];
__device__ bf16 g_WkTH[(size_t)CC * HH * HH], g_WkTL[(size_t)CC * HH * HH];
__device__ bf16 g_McTH[(size_t)CC * HH * HH], g_McTL[(size_t)CC * HH * HH];
__device__ bf16 g_embPH[(size_t)CC * 128 * HH], g_embPL[(size_t)CC * 128 * HH];  // rows>=32 stay 0
__device__ bf16 g_EPH[(size_t)CC * 128 * HH], g_EPL[(size_t)CC * 128 * HH];
__device__ bf16 g_TH[(size_t)CC * BB * SS * HH], g_TL[(size_t)CC * BB * SS * HH];
__device__ float g_wvs[CC * HH];
__device__ float g_vsum[(size_t)CC * BB * SS];

// ------------------------------ helpers -----------------------------------
__device__ __forceinline__ uint32_t smem_to_u32(const void* p) {
    uint32_t a;
    asm("{ .reg .u64 t; cvta.to.shared.u64 t, %1; cvt.u32.u64 %0, t; }" : "=r"(a) : "l"(p));
    return a;
}
__device__ __forceinline__ void split2(float x, bf16& h, bf16& l) {
    h = __float2bfloat16(x);
    l = __float2bfloat16(x - __bfloat162float(h));
}
__device__ __forceinline__ uint32_t packbf(bf16 a, bf16 b) {
    return (uint32_t)__bfloat16_as_ushort(a) | ((uint32_t)__bfloat16_as_ushort(b) << 16);
}
__device__ __forceinline__ void ldsm4(uint32_t* r, uint32_t addr) {
    asm volatile("ldmatrix.sync.aligned.m8n8.x4.shared.b16 {%0,%1,%2,%3}, [%4];"
                 : "=r"(r[0]), "=r"(r[1]), "=r"(r[2]), "=r"(r[3]) : "r"(addr));
}
__device__ __forceinline__ void mma_bf16(float* c, const uint32_t* a, uint32_t b0, uint32_t b1) {
    asm volatile(
        "mma.sync.aligned.m16n8k16.row.col.f32.bf16.bf16.f32 "
        "{%0,%1,%2,%3},{%4,%5,%6,%7},{%8,%9},{%0,%1,%2,%3};"
        : "+f"(c[0]), "+f"(c[1]), "+f"(c[2]), "+f"(c[3])
        : "r"(a[0]), "r"(a[1]), "r"(a[2]), "r"(a[3]), "r"(b0), "r"(b1));
}
#define CPA(s, g) asm volatile("cp.async.cg.shared.global [%0], [%1], 16;" :: "r"(s), "l"(g))
#define CPA_COMMIT() asm volatile("cp.async.commit_group;" ::: "memory")
#define CPA_WAIT1() asm volatile("cp.async.wait_group 1;" ::: "memory")
#define CPA_WAIT0() asm volatile("cp.async.wait_group 0;" ::: "memory")

// ------------------------------ prep kernels ------------------------------
#define HID_BLOCKS 32768   // (BB*SS*HH/4)/256
__global__ void k_cvt(const float* __restrict__ hidden, const float* __restrict__ emb) {
    int bid = blockIdx.x;
    if (bid < HID_BLOCKS) {
        size_t i = (size_t)bid * 256 + threadIdx.x;
        float4 v = ((const float4*)hidden)[i];
        bf16 h0, l0, h1, l1, h2, l2, h3, l3;
        split2(v.x, h0, l0); split2(v.y, h1, l1); split2(v.z, h2, l2); split2(v.w, h3, l3);
        ((uint32_t*)g_hidH)[2 * i] = packbf(h0, h1);
        ((uint32_t*)g_hidH)[2 * i + 1] = packbf(h2, h3);
        ((uint32_t*)g_hidL)[2 * i] = packbf(l0, l1);
        ((uint32_t*)g_hidL)[2 * i + 1] = packbf(l2, l3);
    } else {
        int i = (bid - HID_BLOCKS) * 256 + threadIdx.x;  // float4 index into emb
        int e = i * 4;
        int c = e / (FF * HH);
        int rem = e - c * FF * HH;
        int f = rem / HH, h = rem - f * HH;
        float4 v = ((const float4*)emb)[i];
        bf16 h0, l0, h1, l1, h2, l2, h3, l3;
        split2(v.x, h0, l0); split2(v.y, h1, l1); split2(v.z, h2, l2); split2(v.w, h3, l3);
        size_t o = ((size_t)c * 128 + f) * HH + h;
        *(uint32_t*)&g_embPH[o] = packbf(h0, h1);
        *(uint32_t*)&g_embPH[o + 2] = packbf(h2, h3);
        *(uint32_t*)&g_embPL[o] = packbf(l0, l1);
        *(uint32_t*)&g_embPL[o + 2] = packbf(l2, l3);
    }
}

__global__ void k_tsplit_both(const float* __restrict__ Wq, const float* __restrict__ Wk) {
    __shared__ float t[32][33];
    int z = blockIdx.z;
    int c = z >> 1, W = z & 1;
    const float* I = (W == 0 ? Wq : Wk) + (size_t)c * HH * HH;
    bf16* OH = (W == 0 ? g_WqTH : g_WkTH) + (size_t)c * HH * HH;
    bf16* OL = (W == 0 ? g_WqTL : g_WkTL) + (size_t)c * HH * HH;
    int x = blockIdx.x * 32 + threadIdx.x;
#pragma unroll
    for (int i = threadIdx.y; i < 32; i += 8)
        t[i][threadIdx.x] = I[(size_t)(blockIdx.y * 32 + i) * HH + x];
    __syncthreads();
    int ox = blockIdx.y * 32 + threadIdx.x;
#pragma unroll
    for (int i = threadIdx.y; i < 32; i += 8) {
        float v = t[threadIdx.x][i];
        bf16 h, l;
        split2(v, h, l);
        size_t o = (size_t)(blockIdx.x * 32 + i) * HH + ox;
        OH[o] = h;
        OL[o] = l;
    }
}

__global__ void k_wvsum(const float* __restrict__ Wv) {
    int c = blockIdx.y;
    int h = blockIdx.x * 256 + threadIdx.x;
    const float* W = Wv + (size_t)c * HH * HH;
    float a = 0.f;
#pragma unroll 8
    for (int o = 0; o < HH; ++o) a += W[(size_t)o * HH + h];
    g_wvs[c * HH + h] = a;
}

__global__ void k_vsum(const float* __restrict__ hidden) {
    int w = (blockIdx.x * blockDim.x + threadIdx.x) >> 5;
    int lane = threadIdx.x & 31;
    if (w >= BB * SS) return;
    const float* hr = hidden + (size_t)w * HH;
    float a0 = 0.f, a1 = 0.f;
#pragma unroll 4
    for (int i = lane; i < HH; i += 32) {
        float hv = hr[i];
        a0 += hv * g_wvs[i];
        a1 += hv * g_wvs[HH + i];
    }
#pragma unroll
    for (int off = 16; off; off >>= 1) {
        a0 += __shfl_down_sync(0xFFFFFFFFu, a0, off);
        a1 += __shfl_down_sync(0xFFFFFFFFu, a1, off);
    }
    if (lane == 0) {
        g_vsum[w] = a0;
        g_vsum[(size_t)BB * SS + w] = a1;
    }
}

// ------------------------------ GEMM core ---------------------------------
// C[128,256] = (Ahi+Alo)[128,K] . (Bhi+Blo)[256,K]^T  via 3 bf16 mma splits.
// MODE 0: McT   1: E   2: T   3: main (x vsum -> out)
template <int MODE>
__global__ void __launch_bounds__(256, 1) k_gemm(float* __restrict__ out) {
    extern __shared__ __align__(128) char smem[];
    const uint32_t sb = smem_to_u32(smem);
    const int tid = threadIdx.x, wid = tid >> 5, lane = tid & 31;
    const int bx = blockIdx.x, by = blockIdx.y, bz = blockIdx.z;

    const bf16 *AH, *AL, *BH, *BL;
    if (MODE == 0) {
        size_t cb = (size_t)bz * HH * HH;
        AH = g_WkTH + cb + (size_t)by * 128 * HH; AL = g_WkTL + cb + (size_t)by * 128 * HH;
        BH = g_WqTH + cb + (size_t)bx * 256 * HH; BL = g_WqTL + cb + (size_t)bx * 256 * HH;
    } else if (MODE == 1) {
        AH = g_embPH + (size_t)bz * 128 * HH; AL = g_embPL + (size_t)bz * 128 * HH;
        size_t cb = (size_t)bz * HH * HH;
        BH = g_WkTH + cb + (size_t)bx * 256 * HH; BL = g_WkTL + cb + (size_t)bx * 256 * HH;
    } else if (MODE == 2) {
        AH = g_hidH + (size_t)by * 128 * HH; AL = g_hidL + (size_t)by * 128 * HH;
        size_t cb = (size_t)bz * HH * HH;
        BH = g_McTH + cb + (size_t)bx * 256 * HH; BL = g_McTL + cb + (size_t)bx * 256 * HH;
    } else {
        int c = bz >> 4, b = bz & 15;
        if (by < 16) {
            size_t ro = ((size_t)c * BB * SS + (size_t)b * SS + (size_t)by * 128) * HH;
            AH = g_TH + ro; AL = g_TL + ro;
        } else {
            AH = g_EPH + (size_t)c * 128 * HH; AL = g_EPL + (size_t)c * 128 * HH;
        }
        size_t bo = ((size_t)b * SS + (size_t)bx * 256) * HH;
        BH = g_hidH + bo; BL = g_hidL + bo;
    }

    // loader mapping
    const int lrow = tid >> 1, lhalf = tid & 1;                 // A: 2 thr/row
    const uint32_t sAOff = (uint32_t)(lrow * SRB + lhalf * 64);
    const size_t gAOff = (size_t)lrow * HH + lhalf * 32;
    const uint32_t sBOff = (uint32_t)(tid * SRB);               // B: 1 thr/row
    const size_t gBOff = (size_t)tid * HH;

    // compute mapping: warp tile 64x64
    const int wm = wid >> 2, wn = wid & 3;
    const uint32_t aOff = (uint32_t)((wm * 64 + (lane & 15)) * SRB + ((lane >> 4) << 4));
    const uint32_t bOff = (uint32_t)((wn * 64 + (lane & 7) + ((lane >> 4) & 1) * 8) * SRB +
                                     (((lane >> 3) & 1) << 4));

    float acc[4][8][4] = {};

    // prologue: chunk 0 -> stage 0
    {
#pragma unroll
        for (int i = 0; i < 4; i++) {
            CPA(sb + OFF_AH + sAOff + i * 16, AH + gAOff + i * 8);
            CPA(sb + OFF_AL + sAOff + i * 16, AL + gAOff + i * 8);
        }
#pragma unroll
        for (int i = 0; i < 8; i++) {
            CPA(sb + OFF_BH + sBOff + i * 16, BH + gBOff + i * 8);
            CPA(sb + OFF_BL + sBOff + i * 16, BL + gBOff + i * 8);
        }
        CPA_COMMIT();
    }

    for (int ck = 0; ck < NC; ck++) {
        if (ck + 1 < NC) {
            const uint32_t stg = sb + ((ck + 1) & 1) * STGB;
            const int kof = (ck + 1) * 64;
#pragma unroll
            for (int i = 0; i < 4; i++) {
                CPA(stg + OFF_AH + sAOff + i * 16, AH + gAOff + kof + i * 8);
                CPA(stg + OFF_AL + sAOff + i * 16, AL + gAOff + kof + i * 8);
            }
#pragma unroll
            for (int i = 0; i < 8; i++) {
                CPA(stg + OFF_BH + sBOff + i * 16, BH + gBOff + kof + i * 8);
                CPA(stg + OFF_BL + sBOff + i * 16, BL + gBOff + kof + i * 8);
            }
            CPA_COMMIT();
            CPA_WAIT1();
        } else {
            CPA_WAIT0();
        }
        __syncthreads();

        const uint32_t base = sb + (ck & 1) * STGB;
        const uint32_t pAH = base + OFF_AH + aOff, pAL = base + OFF_AL + aOff;
        const uint32_t pBH = base + OFF_BH + bOff, pBL = base + OFF_BL + bOff;
#pragma unroll
        for (int ka = 0; ka < 4; ka++) {
            uint32_t A[4][4], Bh[4][4], Bl[4][4];
#pragma unroll
            for (int m = 0; m < 4; m++) ldsm4(A[m], pAH + m * (16 * SRB) + ka * 32);
#pragma unroll
            for (int nb = 0; nb < 4; nb++) ldsm4(Bh[nb], pBH + nb * (16 * SRB) + ka * 32);
#pragma unroll
            for (int m = 0; m < 4; m++)
#pragma unroll
                for (int n8 = 0; n8 < 8; n8++)
                    mma_bf16(acc[m][n8], A[m], Bh[n8 >> 1][(n8 & 1) * 2], Bh[n8 >> 1][(n8 & 1) * 2 + 1]);
#pragma unroll
            for (int nb = 0; nb < 4; nb++) ldsm4(Bl[nb], pBL + nb * (16 * SRB) + ka * 32);
#pragma unroll
            for (int m = 0; m < 4; m++)
#pragma unroll
                for (int n8 = 0; n8 < 8; n8++)
                    mma_bf16(acc[m][n8], A[m], Bl[n8 >> 1][(n8 & 1) * 2], Bl[n8 >> 1][(n8 & 1) * 2 + 1]);
#pragma unroll
            for (int m = 0; m < 4; m++) ldsm4(A[m], pAL + m * (16 * SRB) + ka * 32);
#pragma unroll
            for (int m = 0; m < 4; m++)
#pragma unroll
                for (int n8 = 0; n8 < 8; n8++)
                    mma_bf16(acc[m][n8], A[m], Bh[n8 >> 1][(n8 & 1) * 2], Bh[n8 >> 1][(n8 & 1) * 2 + 1]);
        }
        __syncthreads();
    }

    // ------------------------------ epilogue --------------------------------
    const int rBase = wm * 64 + (lane >> 2);
    const int cBase = wn * 64 + (lane & 3) * 2;
    if (MODE == 3) {
        int c = bz >> 4, b = bz & 15;
        const float* vsp = g_vsum + ((size_t)c * BB + b) * SS + bx * 256;
        float* ob = out + ((size_t)b * CC + c) * SF * SS;
#pragma unroll
        for (int m = 0; m < 4; m++) {
            int r0 = by * 128 + m * 16 + rBase;
#pragma unroll
            for (int n8 = 0; n8 < 8; n8++) {
                int cc = cBase + n8 * 8;
                float2 vs = *(const float2*)(vsp + cc);
                size_t col = (size_t)bx * 256 + cc;
                if (r0 < SF) {
                    float2 o;
                    o.x = acc[m][n8][0] * vs.x;
                    o.y = acc[m][n8][1] * vs.y;
                    *(float2*)(ob + (size_t)r0 * SS + col) = o;
                }
                if (r0 + 8 < SF) {
                    float2 o;
                    o.x = acc[m][n8][2] * vs.x;
                    o.y = acc[m][n8][3] * vs.y;
                    *(float2*)(ob + (size_t)(r0 + 8) * SS + col) = o;
                }
            }
        }
    } else {
        bf16 *OH, *OL;
        size_t rowB;
        if (MODE == 0) {
            OH = g_McTH; OL = g_McTL;
            rowB = (size_t)bz * HH * HH + (size_t)(by * 128) * HH;
        } else if (MODE == 1) {
            OH = g_EPH; OL = g_EPL;
            rowB = (size_t)bz * 128 * HH;
        } else {
            OH = g_TH; OL = g_TL;
            rowB = ((size_t)bz * BB * SS + (size_t)by * 128) * HH;
        }
#pragma unroll
        for (int m = 0; m < 4; m++) {
            int r0 = m * 16 + rBase;
#pragma unroll
            for (int n8 = 0; n8 < 8; n8++) {
                int cc = bx * 256 + cBase + n8 * 8;
                bf16 h0, l0, h1, l1;
                split2(acc[m][n8][0], h0, l0);
                split2(acc[m][n8][1], h1, l1);
                *(uint32_t*)&OH[rowB + (size_t)r0 * HH + cc] = packbf(h0, h1);
                *(uint32_t*)&OL[rowB + (size_t)r0 * HH + cc] = packbf(l0, l1);
                split2(acc[m][n8][2], h0, l0);
                split2(acc[m][n8][3], h1, l1);
                *(uint32_t*)&OH[rowB + (size_t)(r0 + 8) * HH + cc] = packbf(h0, h1);
                *(uint32_t*)&OL[rowB + (size_t)(r0 + 8) * HH + cc] = packbf(l0, l1);
            }
        }
    }
}

// ------------------------------ launch ------------------------------------
extern "C" void kernel_launch(void* const* d_in, const int* in_sizes, int n_in,
                              void* d_out, int out_size) {
    const float* hidden = (const float*)d_in[0];
    const float* emb    = (const float*)d_in[1];
    const float* Wk     = (const float*)d_in[2];
    const float* Wq     = (const float*)d_in[3];
    const float* Wv     = (const float*)d_in[4];
    float* out = (float*)d_out;

    cudaFuncSetAttribute(k_gemm<0>, cudaFuncAttributeMaxDynamicSharedMemorySize, SMEM_TOTAL);
    cudaFuncSetAttribute(k_gemm<1>, cudaFuncAttributeMaxDynamicSharedMemorySize, SMEM_TOTAL);
    cudaFuncSetAttribute(k_gemm<2>, cudaFuncAttributeMaxDynamicSharedMemorySize, SMEM_TOTAL);
    cudaFuncSetAttribute(k_gemm<3>, cudaFuncAttributeMaxDynamicSharedMemorySize, SMEM_TOTAL);

    // launch order chosen so the 4th launch (ncu capture slot) is k_gemm<2>
    k_cvt<<<HID_BLOCKS + 64, 256>>>(hidden, emb);                  // 1
    k_tsplit_both<<<dim3(32, 32, 2 * CC), dim3(32, 8)>>>(Wq, Wk);  // 2
    k_gemm<0><<<dim3(4, 8, CC), 256, SMEM_TOTAL>>>(nullptr);       // 3: McT
    k_gemm<2><<<dim3(4, 256, CC), 256, SMEM_TOTAL>>>(nullptr);     // 4: T  <- ncu
    k_gemm<1><<<dim3(4, 1, CC), 256, SMEM_TOTAL>>>(nullptr);       // 5: E
    k_wvsum<<<dim3(HH / 256, CC), 256>>>(Wv);                      // 6
    k_vsum<<<(BB * SS) / 8, 256>>>(hidden);                        // 7
    k_gemm<3><<<dim3(8, 17, CC * BB), 256, SMEM_TOTAL>>>(out);     // 8: scores
}

// round 7
// speedup vs baseline: 2.4332x; 1.1462x over previous
#include <cuda_runtime.h>
#include <cuda_bf16.h>
#include <cstdint>

#define CC 2
#define FF 32
#define HH 1024
#define BB 16
#define SS 2048
#define SF (SS + FF)   // 2080
#define NC 16          // K chunks of 64
#define SRB 144        // smem row bytes (128 data + 16 pad)
// stage layout: Ahi[128] Alo[128] Bhi[256] Blo[256] rows
#define OFF_AH 0
#define OFF_AL (128 * SRB)
#define OFF_BH (256 * SRB)
#define OFF_BL (512 * SRB)
#define STGB (768 * SRB)            // 110592
#define SMEM_TOTAL (2 * STGB)       // 221184
#define NT 512

typedef __nv_bfloat16 bf16;

// ------------------------------ device scratch ----------------------------
__device__ bf16 g_hidH[(size_t)BB * SS * HH], g_hidL[(size_t)BB * SS * HH];
__device__ bf16 g_WqTH[(size_t)CC * HH * HH], g_WqTL[(size_t)CC * HH * HH];
__device__ bf16 g_WkTH[(size_t)CC * HH * HH], g_WkTL[(size_t)CC * HH * HH];
__device__ bf16 g_McTH[(size_t)CC * HH * HH], g_McTL[(size_t)CC * HH * HH];
__device__ bf16 g_embPH[(size_t)CC * 128 * HH], g_embPL[(size_t)CC * 128 * HH];  // rows>=32 stay 0
__device__ bf16 g_EPH[(size_t)CC * 128 * HH], g_EPL[(size_t)CC * 128 * HH];
__device__ bf16 g_TH[(size_t)CC * BB * SS * HH], g_TL[(size_t)CC * BB * SS * HH];
__device__ float g_wvs[CC * HH];
__device__ float g_vsum[(size_t)CC * BB * SS];

// ------------------------------ helpers -----------------------------------
__device__ __forceinline__ uint32_t smem_to_u32(const void* p) {
    uint32_t a;
    asm("{ .reg .u64 t; cvta.to.shared.u64 t, %1; cvt.u32.u64 %0, t; }" : "=r"(a) : "l"(p));
    return a;
}
__device__ __forceinline__ void split2(float x, bf16& h, bf16& l) {
    h = __float2bfloat16(x);
    l = __float2bfloat16(x - __bfloat162float(h));
}
__device__ __forceinline__ uint32_t packbf(bf16 a, bf16 b) {
    return (uint32_t)__bfloat16_as_ushort(a) | ((uint32_t)__bfloat16_as_ushort(b) << 16);
}
__device__ __forceinline__ void ldsm4(uint32_t* r, uint32_t addr) {
    asm volatile("ldmatrix.sync.aligned.m8n8.x4.shared.b16 {%0,%1,%2,%3}, [%4];"
                 : "=r"(r[0]), "=r"(r[1]), "=r"(r[2]), "=r"(r[3]) : "r"(addr));
}
__device__ __forceinline__ void mma_bf16(float* c, const uint32_t* a, uint32_t b0, uint32_t b1) {
    asm volatile(
        "mma.sync.aligned.m16n8k16.row.col.f32.bf16.bf16.f32 "
        "{%0,%1,%2,%3},{%4,%5,%6,%7},{%8,%9},{%0,%1,%2,%3};"
        : "+f"(c[0]), "+f"(c[1]), "+f"(c[2]), "+f"(c[3])
        : "r"(a[0]), "r"(a[1]), "r"(a[2]), "r"(a[3]), "r"(b0), "r"(b1));
}
#define CPA(s, g) asm volatile("cp.async.cg.shared.global [%0], [%1], 16;" :: "r"(s), "l"(g))
#define CPA_COMMIT() asm volatile("cp.async.commit_group;" ::: "memory")
#define CPA_WAIT1() asm volatile("cp.async.wait_group 1;" ::: "memory")
#define CPA_WAIT0() asm volatile("cp.async.wait_group 0;" ::: "memory")

// ------------------------------ prep kernels ------------------------------
#define HID_BLOCKS 32768   // (BB*SS*HH/4)/256
__global__ void k_cvt(const float* __restrict__ hidden, const float* __restrict__ emb) {
    int bid = blockIdx.x;
    if (bid < HID_BLOCKS) {
        size_t i = (size_t)bid * 256 + threadIdx.x;
        float4 v = ((const float4*)hidden)[i];
        bf16 h0, l0, h1, l1, h2, l2, h3, l3;
        split2(v.x, h0, l0); split2(v.y, h1, l1); split2(v.z, h2, l2); split2(v.w, h3, l3);
        ((uint32_t*)g_hidH)[2 * i] = packbf(h0, h1);
        ((uint32_t*)g_hidH)[2 * i + 1] = packbf(h2, h3);
        ((uint32_t*)g_hidL)[2 * i] = packbf(l0, l1);
        ((uint32_t*)g_hidL)[2 * i + 1] = packbf(l2, l3);
    } else {
        int i = (bid - HID_BLOCKS) * 256 + threadIdx.x;
        int e = i * 4;
        int c = e / (FF * HH);
        int rem = e - c * FF * HH;
        int f = rem / HH, h = rem - f * HH;
        float4 v = ((const float4*)emb)[i];
        bf16 h0, l0, h1, l1, h2, l2, h3, l3;
        split2(v.x, h0, l0); split2(v.y, h1, l1); split2(v.z, h2, l2); split2(v.w, h3, l3);
        size_t o = ((size_t)c * 128 + f) * HH + h;
        *(uint32_t*)&g_embPH[o] = packbf(h0, h1);
        *(uint32_t*)&g_embPH[o + 2] = packbf(h2, h3);
        *(uint32_t*)&g_embPL[o] = packbf(l0, l1);
        *(uint32_t*)&g_embPL[o + 2] = packbf(l2, l3);
    }
}

__global__ void k_tsplit_both(const float* __restrict__ Wq, const float* __restrict__ Wk) {
    __shared__ float t[32][33];
    int z = blockIdx.z;
    int c = z >> 1, W = z & 1;
    const float* I = (W == 0 ? Wq : Wk) + (size_t)c * HH * HH;
    bf16* OH = (W == 0 ? g_WqTH : g_WkTH) + (size_t)c * HH * HH;
    bf16* OL = (W == 0 ? g_WqTL : g_WkTL) + (size_t)c * HH * HH;
    int x = blockIdx.x * 32 + threadIdx.x;
#pragma unroll
    for (int i = threadIdx.y; i < 32; i += 8)
        t[i][threadIdx.x] = I[(size_t)(blockIdx.y * 32 + i) * HH + x];
    __syncthreads();
    int ox = blockIdx.y * 32 + threadIdx.x;
#pragma unroll
    for (int i = threadIdx.y; i < 32; i += 8) {
        float v = t[threadIdx.x][i];
        bf16 h, l;
        split2(v, h, l);
        size_t o = (size_t)(blockIdx.x * 32 + i) * HH + ox;
        OH[o] = h;
        OL[o] = l;
    }
}

__global__ void k_wvsum(const float* __restrict__ Wv) {
    int c = blockIdx.y;
    int h = blockIdx.x * 256 + threadIdx.x;
    const float* W = Wv + (size_t)c * HH * HH;
    float a = 0.f;
#pragma unroll 8
    for (int o = 0; o < HH; ++o) a += W[(size_t)o * HH + h];
    g_wvs[c * HH + h] = a;
}

__global__ void k_vsum(const float* __restrict__ hidden) {
    int w = (blockIdx.x * blockDim.x + threadIdx.x) >> 5;
    int lane = threadIdx.x & 31;
    if (w >= BB * SS) return;
    const float* hr = hidden + (size_t)w * HH;
    float a0 = 0.f, a1 = 0.f;
#pragma unroll 4
    for (int i = lane; i < HH; i += 32) {
        float hv = hr[i];
        a0 += hv * g_wvs[i];
        a1 += hv * g_wvs[HH + i];
    }
#pragma unroll
    for (int off = 16; off; off >>= 1) {
        a0 += __shfl_down_sync(0xFFFFFFFFu, a0, off);
        a1 += __shfl_down_sync(0xFFFFFFFFu, a1, off);
    }
    if (lane == 0) {
        g_vsum[w] = a0;
        g_vsum[(size_t)BB * SS + w] = a1;
    }
}

// ------------------------------ GEMM core ---------------------------------
// C[128,256] = (Ahi+Alo)[128,K] . (Bhi+Blo)[256,K]^T  via 3 bf16 mma splits.
// 16 warps, warp grid 2(m) x 8(n), warp tile 64x32.
// MODE 0: McT   1: E   2: T   3: main (x vsum -> out)
template <int MODE>
__global__ void __launch_bounds__(NT, 1) k_gemm(float* __restrict__ out) {
    extern __shared__ __align__(128) char smem[];
    const uint32_t sb = smem_to_u32(smem);
    const int tid = threadIdx.x, wid = tid >> 5, lane = tid & 31;
    const int bx = blockIdx.x, by = blockIdx.y, bz = blockIdx.z;

    const bf16 *AH, *AL, *BH, *BL;
    if (MODE == 0) {
        size_t cb = (size_t)bz * HH * HH;
        AH = g_WkTH + cb + (size_t)by * 128 * HH; AL = g_WkTL + cb + (size_t)by * 128 * HH;
        BH = g_WqTH + cb + (size_t)bx * 256 * HH; BL = g_WqTL + cb + (size_t)bx * 256 * HH;
    } else if (MODE == 1) {
        AH = g_embPH + (size_t)bz * 128 * HH; AL = g_embPL + (size_t)bz * 128 * HH;
        size_t cb = (size_t)bz * HH * HH;
        BH = g_WkTH + cb + (size_t)bx * 256 * HH; BL = g_WkTL + cb + (size_t)bx * 256 * HH;
    } else if (MODE == 2) {
        AH = g_hidH + (size_t)by * 128 * HH; AL = g_hidL + (size_t)by * 128 * HH;
        size_t cb = (size_t)bz * HH * HH;
        BH = g_McTH + cb + (size_t)bx * 256 * HH; BL = g_McTL + cb + (size_t)bx * 256 * HH;
    } else {
        int c = bz >> 4, b = bz & 15;
        if (by < 16) {
            size_t ro = ((size_t)c * BB * SS + (size_t)b * SS + (size_t)by * 128) * HH;
            AH = g_TH + ro; AL = g_TL + ro;
        } else {
            AH = g_EPH + (size_t)c * 128 * HH; AL = g_EPL + (size_t)c * 128 * HH;
        }
        size_t bo = ((size_t)b * SS + (size_t)bx * 256) * HH;
        BH = g_hidH + bo; BL = g_hidL + bo;
    }

    // loader mapping (512 threads):
    // A: 4 thr/row (128 rows), 32B quarter each; B: 2 thr/row (256 rows), 64B half each
    const int arow = tid >> 2, aq = tid & 3;
    const uint32_t sAOff = (uint32_t)(arow * SRB + aq * 32);
    const size_t gAOff = (size_t)arow * HH + aq * 16;
    const int brow = tid >> 1, bhalf = tid & 1;
    const uint32_t sBOff = (uint32_t)(brow * SRB + bhalf * 64);
    const size_t gBOff = (size_t)brow * HH + bhalf * 32;

    // compute mapping: warp tile 64x32
    const int wm = wid >> 3, wn = wid & 7;
    const uint32_t aOff = (uint32_t)((wm * 64 + (lane & 15)) * SRB + ((lane >> 4) << 4));
    const uint32_t bOff = (uint32_t)((wn * 32 + (lane & 7) + ((lane >> 4) & 1) * 8) * SRB +
                                     (((lane >> 3) & 1) << 4));

    float acc[4][4][4] = {};

    // prologue: chunk 0 -> stage 0
    {
#pragma unroll
        for (int i = 0; i < 2; i++) {
            CPA(sb + OFF_AH + sAOff + i * 16, AH + gAOff + i * 8);
            CPA(sb + OFF_AL + sAOff + i * 16, AL + gAOff + i * 8);
        }
#pragma unroll
        for (int i = 0; i < 4; i++) {
            CPA(sb + OFF_BH + sBOff + i * 16, BH + gBOff + i * 8);
            CPA(sb + OFF_BL + sBOff + i * 16, BL + gBOff + i * 8);
        }
        CPA_COMMIT();
    }

    for (int ck = 0; ck < NC; ck++) {
        if (ck + 1 < NC) {
            const uint32_t stg = sb + ((ck + 1) & 1) * STGB;
            const int kof = (ck + 1) * 64;
#pragma unroll
            for (int i = 0; i < 2; i++) {
                CPA(stg + OFF_AH + sAOff + i * 16, AH + gAOff + kof + i * 8);
                CPA(stg + OFF_AL + sAOff + i * 16, AL + gAOff + kof + i * 8);
            }
#pragma unroll
            for (int i = 0; i < 4; i++) {
                CPA(stg + OFF_BH + sBOff + i * 16, BH + gBOff + kof + i * 8);
                CPA(stg + OFF_BL + sBOff + i * 16, BL + gBOff + kof + i * 8);
            }
            CPA_COMMIT();
            CPA_WAIT1();
        } else {
            CPA_WAIT0();
        }
        __syncthreads();

        const uint32_t base = sb + (ck & 1) * STGB;
        const uint32_t pAH = base + OFF_AH + aOff, pAL = base + OFF_AL + aOff;
        const uint32_t pBH = base + OFF_BH + bOff, pBL = base + OFF_BL + bOff;
#pragma unroll
        for (int ka = 0; ka < 4; ka++) {
            uint32_t A[4][4], Bh[2][4], Bl[2][4];
#pragma unroll
            for (int m = 0; m < 4; m++) ldsm4(A[m], pAH + m * (16 * SRB) + ka * 32);
#pragma unroll
            for (int nb = 0; nb < 2; nb++) ldsm4(Bh[nb], pBH + nb * (16 * SRB) + ka * 32);
#pragma unroll
            for (int m = 0; m < 4; m++)
#pragma unroll
                for (int n8 = 0; n8 < 4; n8++)
                    mma_bf16(acc[m][n8], A[m], Bh[n8 >> 1][(n8 & 1) * 2], Bh[n8 >> 1][(n8 & 1) * 2 + 1]);
#pragma unroll
            for (int nb = 0; nb < 2; nb++) ldsm4(Bl[nb], pBL + nb * (16 * SRB) + ka * 32);
#pragma unroll
            for (int m = 0; m < 4; m++)
#pragma unroll
                for (int n8 = 0; n8 < 4; n8++)
                    mma_bf16(acc[m][n8], A[m], Bl[n8 >> 1][(n8 & 1) * 2], Bl[n8 >> 1][(n8 & 1) * 2 + 1]);
#pragma unroll
            for (int m = 0; m < 4; m++) ldsm4(A[m], pAL + m * (16 * SRB) + ka * 32);
#pragma unroll
            for (int m = 0; m < 4; m++)
#pragma unroll
                for (int n8 = 0; n8 < 4; n8++)
                    mma_bf16(acc[m][n8], A[m], Bh[n8 >> 1][(n8 & 1) * 2], Bh[n8 >> 1][(n8 & 1) * 2 + 1]);
        }
        __syncthreads();
    }

    // ------------------------------ epilogue --------------------------------
    const int rBase = wm * 64 + (lane >> 2);
    const int cBase = wn * 32 + (lane & 3) * 2;
    if (MODE == 3) {
        int c = bz >> 4, b = bz & 15;
        const float* vsp = g_vsum + ((size_t)c * BB + b) * SS + bx * 256;
        float* ob = out + ((size_t)b * CC + c) * SF * SS;
#pragma unroll
        for (int m = 0; m < 4; m++) {
            int r0 = by * 128 + m * 16 + rBase;
#pragma unroll
            for (int n8 = 0; n8 < 4; n8++) {
                int cc = cBase + n8 * 8;
                float2 vs = *(const float2*)(vsp + cc);
                size_t col = (size_t)bx * 256 + cc;
                if (r0 < SF) {
                    float2 o;
                    o.x = acc[m][n8][0] * vs.x;
                    o.y = acc[m][n8][1] * vs.y;
                    *(float2*)(ob + (size_t)r0 * SS + col) = o;
                }
                if (r0 + 8 < SF) {
                    float2 o;
                    o.x = acc[m][n8][2] * vs.x;
                    o.y = acc[m][n8][3] * vs.y;
                    *(float2*)(ob + (size_t)(r0 + 8) * SS + col) = o;
                }
            }
        }
    } else {
        bf16 *OH, *OL;
        size_t rowB;
        if (MODE == 0) {
            OH = g_McTH; OL = g_McTL;
            rowB = (size_t)bz * HH * HH + (size_t)(by * 128) * HH;
        } else if (MODE == 1) {
            OH = g_EPH; OL = g_EPL;
            rowB = (size_t)bz * 128 * HH;
        } else {
            OH = g_TH; OL = g_TL;
            rowB = ((size_t)bz * BB * SS + (size_t)by * 128) * HH;
        }
#pragma unroll
        for (int m = 0; m < 4; m++) {
            int r0 = m * 16 + rBase;
#pragma unroll
            for (int n8 = 0; n8 < 4; n8++) {
                int cc = bx * 256 + cBase + n8 * 8;
                bf16 h0, l0, h1, l1;
                split2(acc[m][n8][0], h0, l0);
                split2(acc[m][n8][1], h1, l1);
                *(uint32_t*)&OH[rowB + (size_t)r0 * HH + cc] = packbf(h0, h1);
                *(uint32_t*)&OL[rowB + (size_t)r0 * HH + cc] = packbf(l0, l1);
                split2(acc[m][n8][2], h0, l0);
                split2(acc[m][n8][3], h1, l1);
                *(uint32_t*)&OH[rowB + (size_t)(r0 + 8) * HH + cc] = packbf(h0, h1);
                *(uint32_t*)&OL[rowB + (size_t)(r0 + 8) * HH + cc] = packbf(l0, l1);
            }
        }
    }
}

// ------------------------------ launch ------------------------------------
extern "C" void kernel_launch(void* const* d_in, const int* in_sizes, int n_in,
                              void* d_out, int out_size) {
    const float* hidden = (const float*)d_in[0];
    const float* emb    = (const float*)d_in[1];
    const float* Wk     = (const float*)d_in[2];
    const float* Wq     = (const float*)d_in[3];
    const float* Wv     = (const float*)d_in[4];
    float* out = (float*)d_out;

    cudaFuncSetAttribute(k_gemm<0>, cudaFuncAttributeMaxDynamicSharedMemorySize, SMEM_TOTAL);
    cudaFuncSetAttribute(k_gemm<1>, cudaFuncAttributeMaxDynamicSharedMemorySize, SMEM_TOTAL);
    cudaFuncSetAttribute(k_gemm<2>, cudaFuncAttributeMaxDynamicSharedMemorySize, SMEM_TOTAL);
    cudaFuncSetAttribute(k_gemm<3>, cudaFuncAttributeMaxDynamicSharedMemorySize, SMEM_TOTAL);

    // launch order chosen so the 4th launch (ncu capture slot) is k_gemm<2>
    k_cvt<<<HID_BLOCKS + 64, 256>>>(hidden, emb);                  // 1
    k_tsplit_both<<<dim3(32, 32, 2 * CC), dim3(32, 8)>>>(Wq, Wk);  // 2
    k_gemm<0><<<dim3(4, 8, CC), NT, SMEM_TOTAL>>>(nullptr);        // 3: McT
    k_gemm<2><<<dim3(4, 256, CC), NT, SMEM_TOTAL>>>(nullptr);      // 4: T  <- ncu
    k_gemm<1><<<dim3(4, 1, CC), NT, SMEM_TOTAL>>>(nullptr);        // 5: E
    k_wvsum<<<dim3(HH / 256, CC), 256>>>(Wv);                      // 6
    k_vsum<<<(BB * SS) / 8, 256>>>(hidden);                        // 7
    k_gemm<3><<<dim3(8, 17, CC * BB), NT, SMEM_TOTAL>>>(out);      // 8: scores
}